// round 8
// baseline (speedup 1.0000x reference)
#include <cuda_runtime.h>
#include <cuda_bf16.h>

// Problem constants (fixed by the reference)
#define BB 2
#define LL 1024
#define MM 8
#define NN 16
#define CCH 16          // channels
#define HH 64
#define WW 64
#define CG 2            // channels per block (2 -> 32KB static smem histogram)
#define NCG (CCH / CG)  // 8 channel groups
#define HW (HH * WW)
#define NTHREADS 256

// One block builds the [CG, H, W] histogram slab for one (b,l) anchor and one
// channel group, entirely in shared memory, then streams it to global with
// coalesced float4 streaming stores. Output is covered exactly once -> no
// memset pass, no global atomics; 512MB written once (the HBM floor here).
__global__ __launch_bounds__(NTHREADS) void ht_vote_kernel(
    const float* __restrict__ feats,      // [B,L,N,C]
    const int*   __restrict__ vox_src,    // [B,L,2]
    const int*   __restrict__ vox_dst,    // [B,L,2]
    const int*   __restrict__ idxs_src,   // [B,L,M]
    const int*   __restrict__ idxs_dst,   // [B,L,N]
    float*       __restrict__ out)        // [B,L,C,H,W]
{
    __shared__ float hist[CG * HW];       // 32 KB
    __shared__ int   s_idx[MM];
    __shared__ int   s_vy[MM];
    __shared__ int   s_vx[MM];

    const int bl = blockIdx.x;            // 0 .. B*L-1
    const int cg = blockIdx.y;            // 0 .. NCG-1
    const int b  = bl / LL;
    const int l  = bl - b * LL;
    const int t  = threadIdx.x;

    // ---- phase 0: zero smem histogram; first MM threads load src KNN + voxels
    if (t < MM) {
        const int j = idxs_src[(b * LL + l) * MM + t];
        s_idx[t] = j;
        s_vy[t]  = vox_src[(b * LL + j) * 2 + 0];
        s_vx[t]  = vox_src[(b * LL + j) * 2 + 1];
    }
    float4* h4 = reinterpret_cast<float4*>(hist);
#pragma unroll
    for (int i = 0; i < (CG * HW / 4) / NTHREADS; i++)
        h4[t + i * NTHREADS] = make_float4(0.f, 0.f, 0.f, 0.f);
    __syncthreads();

    // ---- phase 1: vote. Threads 0..127 each own one (m,n) vote: compute the
    // bin and scatter its CG channel weights with smem atomics.
    if (t < MM * NN) {
        const int m = t / NN;
        const int n = t - m * NN;
        const int j = s_idx[m];
        const int d = idxs_dst[(b * LL + j) * NN + n];
        const int vy = vox_dst[(b * LL + d) * 2 + 0];
        const int vx = vox_dst[(b * LL + d) * 2 + 1];
        // voxels are exact small ints: floor(float diff) == int diff
        const int by = vy - s_vy[m] + HH / 2;
        const int bx = vx - s_vx[m] + WW / 2;
        if ((by >= 0) & (by < HH) & (bx >= 0) & (bx < WW)) {
            const int bin = by * WW + bx;
            // two consecutive channel weights; base is 2-aligned -> float2 ok
            const float2 w = *reinterpret_cast<const float2*>(
                &feats[((size_t)(b * LL + j) * NN + n) * CCH + cg * CG]);
            atomicAdd(&hist[0 * HW + bin], w.x);
            atomicAdd(&hist[1 * HW + bin], w.y);
        }
    }
    __syncthreads();

    // ---- phase 2: stream slab to global (contiguous CG*HW floats).
    // __stcs: output is write-once, never re-read here -> streaming stores
    // keep the small index/feature working set resident in L2.
    float4* o4 = reinterpret_cast<float4*>(
        &out[(((size_t)(b * LL + l)) * CCH + cg * CG) * HW]);
#pragma unroll
    for (int i = 0; i < (CG * HW / 4) / NTHREADS; i++)
        __stcs(&o4[t + i * NTHREADS], h4[t + i * NTHREADS]);
}

extern "C" void kernel_launch(void* const* d_in, const int* in_sizes, int n_in,
                              void* d_out, int out_size)
{
    const float* feats    = (const float*)d_in[0];  // feats_src_dst [B,L,N,C]
    const int*   vox_src  = (const int*)  d_in[1];  // voxels_src    [B,L,2]
    const int*   vox_dst  = (const int*)  d_in[2];  // voxels_dst    [B,L,2]
    const int*   idxs_src = (const int*)  d_in[3];  // idxs_src      [B,L,M]
    const int*   idxs_dst = (const int*)  d_in[4];  // idxs_dst      [B,L,N]
    float*       out      = (float*)      d_out;    // [B,L,C,H,W]

    dim3 grid(BB * LL, NCG);
    ht_vote_kernel<<<grid, NTHREADS>>>(feats, vox_src, vox_dst,
                                       idxs_src, idxs_dst, out);
}

// round 13
// speedup vs baseline: 1.1793x; 1.1793x over previous
#include <cuda_runtime.h>
#include <cuda_bf16.h>
#include <cstdint>

// Problem constants (fixed by the reference)
#define BB 2
#define LL 1024
#define MM 8
#define NN 16
#define CCH 16          // channels
#define HH 64
#define WW 64
#define CG 2            // channels per block (2 -> 32KB smem histogram slab)
#define NCG (CCH / CG)  // 8 channel groups
#define HW (HH * WW)
#define NTHREADS 256
#define SLAB_BYTES (CG * HW * 4)   // 32768

// One block builds the [CG, H, W] histogram slab for one (b,l) anchor and one
// channel group in shared memory (smem atomics), then writes it to global with
// a single cp.async.bulk (TMA) shared->global store: the TMA engine reads smem
// and drives the 32KB write, freeing the warps from the LDS->STG issue chain
// that capped round-8 at 5.0 TB/s (DRAM 63.5%).
__global__ __launch_bounds__(NTHREADS) void ht_vote_kernel(
    const float* __restrict__ feats,      // [B,L,N,C]
    const int*   __restrict__ vox_src,    // [B,L,2]
    const int*   __restrict__ vox_dst,    // [B,L,2]
    const int*   __restrict__ idxs_src,   // [B,L,M]
    const int*   __restrict__ idxs_dst,   // [B,L,N]
    float*       __restrict__ out)        // [B,L,C,H,W]
{
    __shared__ alignas(128) float hist[CG * HW];  // 32 KB
    __shared__ int s_idx[MM];
    __shared__ int s_vy[MM];
    __shared__ int s_vx[MM];

    const int bl = blockIdx.x;            // 0 .. B*L-1
    const int cg = blockIdx.y;            // 0 .. NCG-1
    const int b  = bl / LL;
    const int l  = bl - b * LL;
    const int t  = threadIdx.x;

    // ---- phase 0: zero smem histogram; first MM threads load src KNN + voxels
    if (t < MM) {
        const int j = idxs_src[(b * LL + l) * MM + t];
        s_idx[t] = j;
        s_vy[t]  = vox_src[(b * LL + j) * 2 + 0];
        s_vx[t]  = vox_src[(b * LL + j) * 2 + 1];
    }
    float4* h4 = reinterpret_cast<float4*>(hist);
#pragma unroll
    for (int i = 0; i < (CG * HW / 4) / NTHREADS; i++)
        h4[t + i * NTHREADS] = make_float4(0.f, 0.f, 0.f, 0.f);
    __syncthreads();

    // ---- phase 1: vote. Threads 0..127 each own one (m,n) vote: compute the
    // bin and scatter its CG channel weights with smem atomics.
    if (t < MM * NN) {
        const int m = t / NN;
        const int n = t - m * NN;
        const int j = s_idx[m];
        const int d = idxs_dst[(b * LL + j) * NN + n];
        const int vy = vox_dst[(b * LL + d) * 2 + 0];
        const int vx = vox_dst[(b * LL + d) * 2 + 1];
        // voxels are exact small ints: floor(float diff) == int diff
        const int by = vy - s_vy[m] + HH / 2;
        const int bx = vx - s_vx[m] + WW / 2;
        if ((by >= 0) & (by < HH) & (bx >= 0) & (bx < WW)) {
            const int bin = by * WW + bx;
            // two consecutive channel weights; base is 2-aligned -> float2 ok
            const float2 w = *reinterpret_cast<const float2*>(
                &feats[((size_t)(b * LL + j) * NN + n) * CCH + cg * CG]);
            atomicAdd(&hist[0 * HW + bin], w.x);
            atomicAdd(&hist[1 * HW + bin], w.y);
        }
    }
    __syncthreads();

    // Order generic-proxy smem writes (zero-fill + atomics) before the
    // async-proxy TMA read of smem.
    asm volatile("fence.proxy.async.shared::cta;" ::: "memory");

    // ---- phase 2: one bulk shared->global store (32KB, contiguous slab).
    if (t == 0) {
        float* gdst = &out[(((size_t)(b * LL + l)) * CCH + cg * CG) * HW];
        uint32_t saddr = (uint32_t)__cvta_generic_to_shared(hist);
        asm volatile(
            "cp.async.bulk.global.shared::cta.bulk_group [%0], [%1], %2;"
            :: "l"(gdst), "r"(saddr), "n"(SLAB_BYTES) : "memory");
        asm volatile("cp.async.bulk.commit_group;" ::: "memory");
        // Wait only for the smem READ side to finish before the CTA exits and
        // its smem is reused; the global write drains asynchronously.
        asm volatile("cp.async.bulk.wait_group.read 0;" ::: "memory");
    }
}

extern "C" void kernel_launch(void* const* d_in, const int* in_sizes, int n_in,
                              void* d_out, int out_size)
{
    const float* feats    = (const float*)d_in[0];  // feats_src_dst [B,L,N,C]
    const int*   vox_src  = (const int*)  d_in[1];  // voxels_src    [B,L,2]
    const int*   vox_dst  = (const int*)  d_in[2];  // voxels_dst    [B,L,2]
    const int*   idxs_src = (const int*)  d_in[3];  // idxs_src      [B,L,M]
    const int*   idxs_dst = (const int*)  d_in[4];  // idxs_dst      [B,L,N]
    float*       out      = (float*)      d_out;    // [B,L,C,H,W]

    dim3 grid(BB * LL, NCG);
    ht_vote_kernel<<<grid, NTHREADS>>>(feats, vox_src, vox_dst,
                                       idxs_src, idxs_dst, out);
}